// round 1
// baseline (speedup 1.0000x reference)
#include <cuda_runtime.h>
#include <cstdint>
#include <cstddef>

#define B_   2
#define S_   2048
#define HID_ 4096
#define NQ_  32
#define NKV_ 8
#define HD_  128
#define NROW 4096   // B_*S_

// ---------------- scratch (static device globals; no allocations allowed) ---
__device__ float g_Q[(size_t)NROW * HID_];   // 64 MB : Q after proj (+RoPE)
__device__ float g_KV[(size_t)NROW * 2048];  // 32 MB : [K(1024) | V(1024)] per row
__device__ float g_A[(size_t)NROW * HID_];   // 64 MB : attention output (b,s,h*d)

// ---------------------------------------------------------------------------
// C[m,n] = sum_k A[m,k] * B[n,k]   (A: [M,K] row-major, B: [N,K] row-major)
// 128x128x16 tile, 256 threads, 8x8 register microtile.
// ---------------------------------------------------------------------------
__global__ __launch_bounds__(256) void sgemm_abT(const float* __restrict__ A,
                                                 const float* __restrict__ B,
                                                 float* __restrict__ C,
                                                 int M, int N, int K)
{
    constexpr int BM = 128, BN = 128, BK = 16;
    __shared__ float As[BK][BM];
    __shared__ float Bs[BK][BN];

    const int tid = threadIdx.x;
    const int m0 = blockIdx.y * BM;
    const int n0 = blockIdx.x * BN;
    const int ty = tid >> 4;          // 0..15
    const int tx = tid & 15;          // 0..15
    const int lrow = tid >> 2;        // 0..63
    const int lc   = (tid & 3) << 2;  // 0,4,8,12

    float acc[8][8];
#pragma unroll
    for (int i = 0; i < 8; i++)
#pragma unroll
        for (int j = 0; j < 8; j++) acc[i][j] = 0.f;

    const float* Ap = A + (size_t)m0 * K;
    const float* Bp = B + (size_t)n0 * K;

    for (int k0 = 0; k0 < K; k0 += BK) {
#pragma unroll
        for (int h = 0; h < 2; h++) {
            int r = lrow + h * 64;
            float4 va = *(const float4*)&Ap[(size_t)r * K + k0 + lc];
            As[lc + 0][r] = va.x; As[lc + 1][r] = va.y;
            As[lc + 2][r] = va.z; As[lc + 3][r] = va.w;
            float4 vb = *(const float4*)&Bp[(size_t)r * K + k0 + lc];
            Bs[lc + 0][r] = vb.x; Bs[lc + 1][r] = vb.y;
            Bs[lc + 2][r] = vb.z; Bs[lc + 3][r] = vb.w;
        }
        __syncthreads();
#pragma unroll
        for (int kk = 0; kk < BK; kk++) {
            float a[8], b[8];
            *(float4*)&a[0] = *(const float4*)&As[kk][ty * 8];
            *(float4*)&a[4] = *(const float4*)&As[kk][ty * 8 + 4];
            *(float4*)&b[0] = *(const float4*)&Bs[kk][tx * 8];
            *(float4*)&b[4] = *(const float4*)&Bs[kk][tx * 8 + 4];
#pragma unroll
            for (int i = 0; i < 8; i++)
#pragma unroll
                for (int j = 0; j < 8; j++) acc[i][j] += a[i] * b[j];
        }
        __syncthreads();
    }

#pragma unroll
    for (int i = 0; i < 8; i++) {
        float* cp = &C[(size_t)(m0 + ty * 8 + i) * N + n0 + tx * 8];
        *(float4*)&cp[0] = make_float4(acc[i][0], acc[i][1], acc[i][2], acc[i][3]);
        *(float4*)&cp[4] = make_float4(acc[i][4], acc[i][5], acc[i][6], acc[i][7]);
    }
}

// ---------------------------------------------------------------------------
// In-place RoPE. X viewed as [NROW][nheads][128]; cos/sin indexed by the
// (b=0,h=0) slice: value depends only on (s, d).  out[d]   = x1*c - x2*s
//                                                 out[d+64]= x2*c + x1*s
// ---------------------------------------------------------------------------
__global__ __launch_bounds__(256) void rope_kernel(float* __restrict__ X,
                                                   int nheads, int rowstride,
                                                   const float* __restrict__ ct,
                                                   const float* __restrict__ st,
                                                   int total)
{
    int idx = blockIdx.x * blockDim.x + threadIdx.x;
    if (idx >= total) return;
    int d = idx & 63;
    int h = (idx >> 6) % nheads;
    int n = idx / (64 * nheads);
    int s = n & (S_ - 1);
    float c1 = ct[s * HD_ + d],      s1 = st[s * HD_ + d];
    float c2 = ct[s * HD_ + d + 64], s2 = st[s * HD_ + d + 64];
    float* p = X + (size_t)n * rowstride + h * HD_;
    float x1 = p[d], x2 = p[d + 64];
    p[d]      = x1 * c1 - x2 * s1;
    p[d + 64] = x2 * c2 + x1 * s2;
}

// ---------------------------------------------------------------------------
// Flash attention, fp32, causal GQA (4 q-heads per kv-head).
// CTA = 64 q-rows of one (batch, q-head); streams 64-wide K/V tiles.
// Dynamic smem: sQ[128][68] (transposed, pre-scaled), sKV (K transposed /
// V natural, reused), sS[64][68] scores->probs.  87040 bytes.
// ---------------------------------------------------------------------------
__global__ __launch_bounds__(256) void flash_kernel(const float* __restrict__ Q,
                                                    const float* __restrict__ KV,
                                                    float* __restrict__ O)
{
    extern __shared__ float sm[];
    float* sQ  = sm;              // [d*68 + r]
    float* sKV = sm + 128 * 68;   // K: [d*68 + j] ; V: [j*128 + c]
    float* sS  = sKV + 128 * 68;  // [r*68 + j]

    const float SCALE = 0.08838834764831845f; // 1/sqrt(128)
    const int tid = threadIdx.x;
    const int qt = blockIdx.x;    // q tile 0..31
    const int hq = blockIdx.y;    // 0..31
    const int b  = blockIdx.z;    // 0..1
    const int hk = hq >> 2;
    const int i0 = qt * 64;

    const size_t qbase = ((size_t)(b * S_ + i0)) * HID_ + (size_t)hq * HD_;
    const size_t kbase = ((size_t)(b * S_)) * 2048 + (size_t)hk * HD_;
    const size_t vbase = kbase + 1024;

    // load Q tile, transposed + pre-scaled
#pragma unroll
    for (int it = 0; it < 8; it++) {
        int f = tid + it * 256;
        int r = f & 63;
        int d = (f >> 6) * 4;
        float4 v = *(const float4*)&Q[qbase + (size_t)r * HID_ + d];
        sQ[(d + 0) * 68 + r] = v.x * SCALE;
        sQ[(d + 1) * 68 + r] = v.y * SCALE;
        sQ[(d + 2) * 68 + r] = v.z * SCALE;
        sQ[(d + 3) * 68 + r] = v.w * SCALE;
    }

    const int w = tid >> 5, lane = tid & 31;
    const int r0 = w * 8;             // this warp owns rows r0..r0+7
    const int ty = tid >> 4, tx = tid & 15;

    float m_i[8], l_i[8], acc[8][4];
#pragma unroll
    for (int i = 0; i < 8; i++) {
        m_i[i] = -1e30f; l_i[i] = 0.f;
#pragma unroll
        for (int j = 0; j < 4; j++) acc[i][j] = 0.f;
    }

    const int ntiles = qt + 1;        // causal: only tiles with j0 <= i0
    for (int t = 0; t < ntiles; t++) {
        const int j0 = t * 64;
        __syncthreads();                              // prev PV done / Q load done

        // load K tile transposed: sKV[d][j]
#pragma unroll
        for (int it = 0; it < 8; it++) {
            int f = tid + it * 256;
            int j = f & 63;
            int d = (f >> 6) * 4;
            float4 v = *(const float4*)&KV[kbase + (size_t)(j0 + j) * 2048 + d];
            sKV[(d + 0) * 68 + j] = v.x;
            sKV[(d + 1) * 68 + j] = v.y;
            sKV[(d + 2) * 68 + j] = v.z;
            sKV[(d + 3) * 68 + j] = v.w;
        }
        __syncthreads();

        // S = (Q*scale) K^T  -> sS
        float sacc[4][4];
#pragma unroll
        for (int i = 0; i < 4; i++)
#pragma unroll
            for (int j = 0; j < 4; j++) sacc[i][j] = 0.f;
#pragma unroll 8
        for (int d = 0; d < 128; d++) {
            float a[4], bb[4];
            *(float4*)a  = *(const float4*)&sQ[d * 68 + ty * 4];
            *(float4*)bb = *(const float4*)&sKV[d * 68 + tx * 4];
#pragma unroll
            for (int i = 0; i < 4; i++)
#pragma unroll
                for (int j = 0; j < 4; j++) sacc[i][j] += a[i] * bb[j];
        }
#pragma unroll
        for (int i = 0; i < 4; i++)
            *(float4*)&sS[(ty * 4 + i) * 68 + tx * 4] =
                make_float4(sacc[i][0], sacc[i][1], sacc[i][2], sacc[i][3]);
        __syncthreads();                              // S done; K no longer needed

        // load V tile (natural layout) into sKV — overlapped with softmax below
#pragma unroll
        for (int it = 0; it < 8; it++) {
            int f = tid + it * 256;
            int j = f >> 5;
            int c = (f & 31) * 4;
            float4 v = *(const float4*)&KV[vbase + (size_t)(j0 + j) * 2048 + c];
            *(float4*)&sKV[j * 128 + c] = v;
        }

        // online softmax update, per-warp rows
        const bool diag = (t == ntiles - 1);
#pragma unroll
        for (int rr = 0; rr < 8; rr++) {
            int r = r0 + rr;
            float s1 = sS[r * 68 + lane];
            float s2 = sS[r * 68 + 32 + lane];
            if (diag) {                               // j0 == i0: mask col > row
                if (lane > r)      s1 = -1e30f;
                if (lane + 32 > r) s2 = -1e30f;
            }
            float mx = fmaxf(s1, s2);
#pragma unroll
            for (int o = 16; o > 0; o >>= 1)
                mx = fmaxf(mx, __shfl_xor_sync(0xffffffffu, mx, o));
            float mnew = fmaxf(m_i[rr], mx);
            float p1 = __expf(s1 - mnew);
            float p2 = __expf(s2 - mnew);
            float rs = p1 + p2;
#pragma unroll
            for (int o = 16; o > 0; o >>= 1)
                rs += __shfl_xor_sync(0xffffffffu, rs, o);
            float corr = __expf(m_i[rr] - mnew);
            l_i[rr] = l_i[rr] * corr + rs;
            m_i[rr] = mnew;
#pragma unroll
            for (int c = 0; c < 4; c++) acc[rr][c] *= corr;
            sS[r * 68 + lane]      = p1;
            sS[r * 68 + 32 + lane] = p2;
        }
        __syncthreads();                              // V loaded, P written

        // acc += P @ V   (lane owns cols {lane, +32, +64, +96})
#pragma unroll 4
        for (int j = 0; j < 64; j++) {
            float v0 = sKV[j * 128 + lane];
            float v1 = sKV[j * 128 + lane + 32];
            float v2 = sKV[j * 128 + lane + 64];
            float v3 = sKV[j * 128 + lane + 96];
#pragma unroll
            for (int rr = 0; rr < 8; rr++) {
                float p = sS[(r0 + rr) * 68 + j];
                acc[rr][0] += p * v0;
                acc[rr][1] += p * v1;
                acc[rr][2] += p * v2;
                acc[rr][3] += p * v3;
            }
        }
    }

    const size_t obase = ((size_t)(b * S_ + i0)) * HID_ + (size_t)hq * HD_;
#pragma unroll
    for (int rr = 0; rr < 8; rr++) {
        float inv = 1.f / l_i[rr];
        size_t rb = obase + (size_t)(r0 + rr) * HID_;
        O[rb + lane]      = acc[rr][0] * inv;
        O[rb + lane + 32] = acc[rr][1] * inv;
        O[rb + lane + 64] = acc[rr][2] * inv;
        O[rb + lane + 96] = acc[rr][3] * inv;
    }
}

// ---------------------------------------------------------------------------
extern "C" void kernel_launch(void* const* d_in, const int* in_sizes, int n_in,
                              void* d_out, int out_size)
{
    const float* x    = (const float*)d_in[0];
    const float* cosT = (const float*)d_in[1];   // [B,NQ,S,HD]; slice (0,0,s,d)
    const float* sinT = (const float*)d_in[2];
    // d_in[3] = attention_mask (pure causal -1e9; handled analytically)
    const float* Wq   = (const float*)d_in[4];   // [4096,4096]
    const float* Wkv  = (const float*)d_in[5];   // [2048,4096]
    const float* Wo   = (const float*)d_in[6];   // [4096,4096]
    float* out = (float*)d_out;

    float *Qp, *KVp, *Ap;
    cudaGetSymbolAddress((void**)&Qp,  g_Q);
    cudaGetSymbolAddress((void**)&KVp, g_KV);
    cudaGetSymbolAddress((void**)&Ap,  g_A);

    const int FLASH_SMEM = (128 * 68 * 2 + 64 * 68) * 4;   // 87040 B
    cudaFuncSetAttribute(flash_kernel,
                         cudaFuncAttributeMaxDynamicSharedMemorySize, FLASH_SMEM);

    dim3 blk(256);
    // Q = x @ Wq^T            [4096,4096]
    sgemm_abT<<<dim3(32, 32), blk>>>(x, Wq, Qp, NROW, HID_, HID_);
    // [K|V] = x @ Wkv^T       [4096,2048]
    sgemm_abT<<<dim3(16, 32), blk>>>(x, Wkv, KVp, NROW, 2048, HID_);
    // RoPE in place (Q: 32 heads, K: first 1024 cols of KV = 8 heads)
    rope_kernel<<<(NROW * NQ_ * 64) / 256, blk>>>(Qp, NQ_, HID_, cosT, sinT,
                                                  NROW * NQ_ * 64);
    rope_kernel<<<(NROW * NKV_ * 64) / 256, blk>>>(KVp, NKV_, 2048, cosT, sinT,
                                                   NROW * NKV_ * 64);
    // causal GQA flash attention -> g_A laid out [b,s, hq*128+d]
    flash_kernel<<<dim3(32, NQ_, B_), blk, FLASH_SMEM>>>(Qp, KVp, Ap);
    // out = A @ Wo^T
    sgemm_abT<<<dim3(32, 32), blk>>>(Ap, Wo, out, NROW, HID_, HID_);
}

// round 3
// speedup vs baseline: 2.2009x; 2.2009x over previous
#include <cuda_runtime.h>
#include <cstdint>
#include <cstddef>

#define B_   2
#define S_   2048
#define HID_ 4096
#define NQ_  32
#define NKV_ 8
#define HD_  128
#define NROW 4096   // B_*S_

// ---------------- scratch (static device globals; no allocations allowed) ---
__device__ float g_Q[(size_t)NROW * HID_];   // 64 MB
__device__ float g_KV[(size_t)NROW * 2048];  // 32 MB : [K(1024) | V(1024)]
__device__ float g_A[(size_t)NROW * HID_];   // 64 MB

// ===========================================================================
// TF32 tensor-core GEMM:  C[m,n] = sum_k A[m,k]*B[n,k]
// CTA tile 128x128x32, 256 thr (8 warps = 4x2), mma.sync.m16n8k8.tf32,
// cp.async double-buffered. smem stride 36 floats -> conflict-free LDS.
// ===========================================================================
#define BM 128
#define BN 128
#define BK 32
#define PAD 36
#define STAGE_F (128 * PAD)          // floats per tile-stage

__device__ __forceinline__ uint32_t f2tf32(float f) {
    uint32_t u;
    asm("cvt.rna.tf32.f32 %0, %1;" : "=r"(u) : "f"(f));
    return u;
}

__device__ __forceinline__ void cp_async16(uint32_t smem_dst, const void* gptr) {
    asm volatile("cp.async.cg.shared.global [%0], [%1], 16;\n"
                 :: "r"(smem_dst), "l"(gptr));
}
__device__ __forceinline__ void cp_commit() {
    asm volatile("cp.async.commit_group;\n" ::: "memory");
}
template <int N>
__device__ __forceinline__ void cp_wait() {
    asm volatile("cp.async.wait_group %0;\n" :: "n"(N) : "memory");
}

__device__ __forceinline__ void mma_tf32(float c[4], const uint32_t a[4],
                                         const uint32_t b[2]) {
    asm volatile(
        "mma.sync.aligned.m16n8k8.row.col.f32.tf32.tf32.f32 "
        "{%0,%1,%2,%3}, {%4,%5,%6,%7}, {%8,%9}, {%0,%1,%2,%3};\n"
        : "+f"(c[0]), "+f"(c[1]), "+f"(c[2]), "+f"(c[3])
        : "r"(a[0]), "r"(a[1]), "r"(a[2]), "r"(a[3]), "r"(b[0]), "r"(b[1]));
}

__global__ __launch_bounds__(256) void tgemm_abT(const float* __restrict__ A,
                                                 const float* __restrict__ B,
                                                 float* __restrict__ C,
                                                 int M, int N, int K)
{
    extern __shared__ float sm[];
    float* As = sm;                  // [2][128][PAD]
    float* Bs = sm + 2 * STAGE_F;    // [2][128][PAD]

    const int tid  = threadIdx.x;
    const int m0   = blockIdx.y * BM;
    const int n0   = blockIdx.x * BN;
    const int warp = tid >> 5, lane = tid & 31;
    const int wm   = (warp >> 1) * 32;     // warp M offset (4 warps over M)
    const int wn   = (warp & 1) * 64;      // warp N offset (2 warps over N)
    const int g    = lane >> 2;            // 0..7
    const int tg   = lane & 3;             // 0..3

    const int lr = tid >> 3;               // 0..31  (load row)
    const int lk = (tid & 7) * 4;          // 0..28  (load k, float4)

    uint32_t sA = (uint32_t)__cvta_generic_to_shared(As);
    uint32_t sB = (uint32_t)__cvta_generic_to_shared(Bs);

    float acc[2][8][4];
#pragma unroll
    for (int mt = 0; mt < 2; mt++)
#pragma unroll
        for (int nt = 0; nt < 8; nt++)
#pragma unroll
            for (int i = 0; i < 4; i++) acc[mt][nt][i] = 0.f;

    const int nk = K / BK;

    auto issue = [&](int stage, int k0) {
        uint32_t da = sA + (stage * STAGE_F) * 4;
        uint32_t db = sB + (stage * STAGE_F) * 4;
#pragma unroll
        for (int h = 0; h < 4; h++) {
            int r = lr + 32 * h;
            cp_async16(da + (r * PAD + lk) * 4,
                       &A[(size_t)(m0 + r) * K + k0 + lk]);
            cp_async16(db + (r * PAD + lk) * 4,
                       &B[(size_t)(n0 + r) * K + k0 + lk]);
        }
        cp_commit();
    };

    issue(0, 0);

    for (int kt = 0; kt < nk; kt++) {
        if (kt + 1 < nk) issue((kt + 1) & 1, (kt + 1) * BK);
        if (kt + 1 < nk) cp_wait<1>(); else cp_wait<0>();
        __syncthreads();

        const float* a_ = As + (kt & 1) * STAGE_F;
        const float* b_ = Bs + (kt & 1) * STAGE_F;

#pragma unroll
        for (int kk = 0; kk < 4; kk++) {
            const int kb = kk * 8 + tg;
            uint32_t af[2][4], bf[8][2];
#pragma unroll
            for (int mt = 0; mt < 2; mt++) {
                int row = wm + mt * 16 + g;
                af[mt][0] = f2tf32(a_[row * PAD + kb]);
                af[mt][1] = f2tf32(a_[(row + 8) * PAD + kb]);
                af[mt][2] = f2tf32(a_[row * PAD + kb + 4]);
                af[mt][3] = f2tf32(a_[(row + 8) * PAD + kb + 4]);
            }
#pragma unroll
            for (int nt = 0; nt < 8; nt++) {
                int col = wn + nt * 8 + g;
                bf[nt][0] = f2tf32(b_[col * PAD + kb]);
                bf[nt][1] = f2tf32(b_[col * PAD + kb + 4]);
            }
#pragma unroll
            for (int mt = 0; mt < 2; mt++)
#pragma unroll
                for (int nt = 0; nt < 8; nt++)
                    mma_tf32(acc[mt][nt], af[mt], bf[nt]);
        }
        __syncthreads();
    }

    // epilogue: c0,c1 at (row, 2*tg), c2,c3 at (row+8, 2*tg)
#pragma unroll
    for (int mt = 0; mt < 2; mt++) {
        int row = m0 + wm + mt * 16 + g;
#pragma unroll
        for (int nt = 0; nt < 8; nt++) {
            int col = n0 + wn + nt * 8 + tg * 2;
            *(float2*)&C[(size_t)row * N + col] =
                make_float2(acc[mt][nt][0], acc[mt][nt][1]);
            *(float2*)&C[(size_t)(row + 8) * N + col] =
                make_float2(acc[mt][nt][2], acc[mt][nt][3]);
        }
    }
}

// ---------------------------------------------------------------------------
// In-place RoPE (value depends only on (s,d); index the [0,0] slice).
// ---------------------------------------------------------------------------
__global__ __launch_bounds__(256) void rope_kernel(float* __restrict__ X,
                                                   int nheads, int rowstride,
                                                   const float* __restrict__ ct,
                                                   const float* __restrict__ st,
                                                   int total)
{
    int idx = blockIdx.x * blockDim.x + threadIdx.x;
    if (idx >= total) return;
    int d = idx & 63;
    int h = (idx >> 6) % nheads;
    int n = idx / (64 * nheads);
    int s = n & (S_ - 1);
    float c1 = ct[s * HD_ + d],      s1 = st[s * HD_ + d];
    float c2 = ct[s * HD_ + d + 64], s2 = st[s * HD_ + d + 64];
    float* p = X + (size_t)n * rowstride + h * HD_;
    float x1 = p[d], x2 = p[d + 64];
    p[d]      = x1 * c1 - x2 * s1;
    p[d + 64] = x2 * c2 + x1 * s2;
}

// ---------------------------------------------------------------------------
// Flash attention, fp32, causal GQA (unchanged from R1).
// ---------------------------------------------------------------------------
__global__ __launch_bounds__(256) void flash_kernel(const float* __restrict__ Q,
                                                    const float* __restrict__ KV,
                                                    float* __restrict__ O)
{
    extern __shared__ float sm[];
    float* sQ  = sm;              // [d*68 + r]
    float* sKV = sm + 128 * 68;   // K: [d*68 + j] ; V: [j*128 + c]
    float* sS  = sKV + 128 * 68;  // [r*68 + j]

    const float SCALE = 0.08838834764831845f;
    const int tid = threadIdx.x;
    const int qt = blockIdx.x;
    const int hq = blockIdx.y;
    const int b  = blockIdx.z;
    const int hk = hq >> 2;
    const int i0 = qt * 64;

    const size_t qbase = ((size_t)(b * S_ + i0)) * HID_ + (size_t)hq * HD_;
    const size_t kbase = ((size_t)(b * S_)) * 2048 + (size_t)hk * HD_;
    const size_t vbase = kbase + 1024;

#pragma unroll
    for (int it = 0; it < 8; it++) {
        int f = tid + it * 256;
        int r = f & 63;
        int d = (f >> 6) * 4;
        float4 v = *(const float4*)&Q[qbase + (size_t)r * HID_ + d];
        sQ[(d + 0) * 68 + r] = v.x * SCALE;
        sQ[(d + 1) * 68 + r] = v.y * SCALE;
        sQ[(d + 2) * 68 + r] = v.z * SCALE;
        sQ[(d + 3) * 68 + r] = v.w * SCALE;
    }

    const int w = tid >> 5, lane = tid & 31;
    const int r0 = w * 8;
    const int ty = tid >> 4, tx = tid & 15;

    float m_i[8], l_i[8], acc[8][4];
#pragma unroll
    for (int i = 0; i < 8; i++) {
        m_i[i] = -1e30f; l_i[i] = 0.f;
#pragma unroll
        for (int j = 0; j < 4; j++) acc[i][j] = 0.f;
    }

    const int ntiles = qt + 1;
    for (int t = 0; t < ntiles; t++) {
        const int j0 = t * 64;
        __syncthreads();

#pragma unroll
        for (int it = 0; it < 8; it++) {
            int f = tid + it * 256;
            int j = f & 63;
            int d = (f >> 6) * 4;
            float4 v = *(const float4*)&KV[kbase + (size_t)(j0 + j) * 2048 + d];
            sKV[(d + 0) * 68 + j] = v.x;
            sKV[(d + 1) * 68 + j] = v.y;
            sKV[(d + 2) * 68 + j] = v.z;
            sKV[(d + 3) * 68 + j] = v.w;
        }
        __syncthreads();

        float sacc[4][4];
#pragma unroll
        for (int i = 0; i < 4; i++)
#pragma unroll
            for (int j = 0; j < 4; j++) sacc[i][j] = 0.f;
#pragma unroll 8
        for (int d = 0; d < 128; d++) {
            float a[4], bb[4];
            *(float4*)a  = *(const float4*)&sQ[d * 68 + ty * 4];
            *(float4*)bb = *(const float4*)&sKV[d * 68 + tx * 4];
#pragma unroll
            for (int i = 0; i < 4; i++)
#pragma unroll
                for (int j = 0; j < 4; j++) sacc[i][j] += a[i] * bb[j];
        }
#pragma unroll
        for (int i = 0; i < 4; i++)
            *(float4*)&sS[(ty * 4 + i) * 68 + tx * 4] =
                make_float4(sacc[i][0], sacc[i][1], sacc[i][2], sacc[i][3]);
        __syncthreads();

#pragma unroll
        for (int it = 0; it < 8; it++) {
            int f = tid + it * 256;
            int j = f >> 5;
            int c = (f & 31) * 4;
            float4 v = *(const float4*)&KV[vbase + (size_t)(j0 + j) * 2048 + c];
            *(float4*)&sKV[j * 128 + c] = v;
        }

        const bool diag = (t == ntiles - 1);
#pragma unroll
        for (int rr = 0; rr < 8; rr++) {
            int r = r0 + rr;
            float s1 = sS[r * 68 + lane];
            float s2 = sS[r * 68 + 32 + lane];
            if (diag) {
                if (lane > r)      s1 = -1e30f;
                if (lane + 32 > r) s2 = -1e30f;
            }
            float mx = fmaxf(s1, s2);
#pragma unroll
            for (int o = 16; o > 0; o >>= 1)
                mx = fmaxf(mx, __shfl_xor_sync(0xffffffffu, mx, o));
            float mnew = fmaxf(m_i[rr], mx);
            float p1 = __expf(s1 - mnew);
            float p2 = __expf(s2 - mnew);
            float rs = p1 + p2;
#pragma unroll
            for (int o = 16; o > 0; o >>= 1)
                rs += __shfl_xor_sync(0xffffffffu, rs, o);
            float corr = __expf(m_i[rr] - mnew);
            l_i[rr] = l_i[rr] * corr + rs;
            m_i[rr] = mnew;
#pragma unroll
            for (int c = 0; c < 4; c++) acc[rr][c] *= corr;
            sS[r * 68 + lane]      = p1;
            sS[r * 68 + 32 + lane] = p2;
        }
        __syncthreads();

#pragma unroll 4
        for (int j = 0; j < 64; j++) {
            float v0 = sKV[j * 128 + lane];
            float v1 = sKV[j * 128 + lane + 32];
            float v2 = sKV[j * 128 + lane + 64];
            float v3 = sKV[j * 128 + lane + 96];
#pragma unroll
            for (int rr = 0; rr < 8; rr++) {
                float p = sS[(r0 + rr) * 68 + j];
                acc[rr][0] += p * v0;
                acc[rr][1] += p * v1;
                acc[rr][2] += p * v2;
                acc[rr][3] += p * v3;
            }
        }
    }

    const size_t obase = ((size_t)(b * S_ + i0)) * HID_ + (size_t)hq * HD_;
#pragma unroll
    for (int rr = 0; rr < 8; rr++) {
        float inv = 1.f / l_i[rr];
        size_t rb = obase + (size_t)(r0 + rr) * HID_;
        O[rb + lane]      = acc[rr][0] * inv;
        O[rb + lane + 32] = acc[rr][1] * inv;
        O[rb + lane + 64] = acc[rr][2] * inv;
        O[rb + lane + 96] = acc[rr][3] * inv;
    }
}

// ---------------------------------------------------------------------------
extern "C" void kernel_launch(void* const* d_in, const int* in_sizes, int n_in,
                              void* d_out, int out_size)
{
    const float* x    = (const float*)d_in[0];
    const float* cosT = (const float*)d_in[1];
    const float* sinT = (const float*)d_in[2];
    // d_in[3] = attention_mask (pure causal; handled analytically)
    const float* Wq   = (const float*)d_in[4];
    const float* Wkv  = (const float*)d_in[5];
    const float* Wo   = (const float*)d_in[6];
    float* out = (float*)d_out;

    float *Qp, *KVp, *Ap;
    cudaGetSymbolAddress((void**)&Qp,  g_Q);
    cudaGetSymbolAddress((void**)&KVp, g_KV);
    cudaGetSymbolAddress((void**)&Ap,  g_A);

    const int GEMM_SMEM  = 4 * STAGE_F * 4;                 // 73728 B
    const int FLASH_SMEM = (128 * 68 * 2 + 64 * 68) * 4;    // 87040 B
    cudaFuncSetAttribute(tgemm_abT,
                         cudaFuncAttributeMaxDynamicSharedMemorySize, GEMM_SMEM);
    cudaFuncSetAttribute(flash_kernel,
                         cudaFuncAttributeMaxDynamicSharedMemorySize, FLASH_SMEM);

    dim3 blk(256);
    // Q = x @ Wq^T            [4096,4096]
    tgemm_abT<<<dim3(32, 32), blk, GEMM_SMEM>>>(x, Wq, Qp, NROW, HID_, HID_);
    // [K|V] = x @ Wkv^T       [4096,2048]
    tgemm_abT<<<dim3(16, 32), blk, GEMM_SMEM>>>(x, Wkv, KVp, NROW, 2048, HID_);
    // RoPE in place
    rope_kernel<<<(NROW * NQ_ * 64) / 256, blk>>>(Qp, NQ_, HID_, cosT, sinT,
                                                  NROW * NQ_ * 64);
    rope_kernel<<<(NROW * NKV_ * 64) / 256, blk>>>(KVp, NKV_, 2048, cosT, sinT,
                                                   NROW * NKV_ * 64);
    // causal GQA flash attention -> g_A
    flash_kernel<<<dim3(32, NQ_, B_), blk, FLASH_SMEM>>>(Qp, KVp, Ap);
    // out = A @ Wo^T
    tgemm_abT<<<dim3(32, 32), blk, GEMM_SMEM>>>(Ap, Wo, out, NROW, HID_, HID_);
}

// round 4
// speedup vs baseline: 2.5106x; 1.1407x over previous
#include <cuda_runtime.h>
#include <cstdint>
#include <cstddef>

#define B_   2
#define S_   2048
#define HID_ 4096
#define NQ_  32
#define NKV_ 8
#define HD_  128
#define NROW 4096   // B_*S_

// ---------------- scratch (static device globals; no allocations allowed) ---
__device__ float g_Q[(size_t)NROW * HID_];   // 64 MB
__device__ float g_KV[(size_t)NROW * 2048];  // 32 MB : [K(1024) | V(1024)]
__device__ float g_A[(size_t)NROW * HID_];   // 64 MB

// ---------------- common PTX helpers ---------------------------------------
__device__ __forceinline__ uint32_t f2tf32(float f) {
    uint32_t u;
    asm("cvt.rna.tf32.f32 %0, %1;" : "=r"(u) : "f"(f));
    return u;
}
__device__ __forceinline__ void cp_async16(uint32_t smem_dst, const void* gptr) {
    asm volatile("cp.async.cg.shared.global [%0], [%1], 16;\n"
                 :: "r"(smem_dst), "l"(gptr));
}
__device__ __forceinline__ void cp_commit() {
    asm volatile("cp.async.commit_group;\n" ::: "memory");
}
template <int N>
__device__ __forceinline__ void cp_wait() {
    asm volatile("cp.async.wait_group %0;\n" :: "n"(N) : "memory");
}
__device__ __forceinline__ void mma_tf32(float c[4], const uint32_t a[4],
                                         const uint32_t b[2]) {
    asm volatile(
        "mma.sync.aligned.m16n8k8.row.col.f32.tf32.tf32.f32 "
        "{%0,%1,%2,%3}, {%4,%5,%6,%7}, {%8,%9}, {%0,%1,%2,%3};\n"
        : "+f"(c[0]), "+f"(c[1]), "+f"(c[2]), "+f"(c[3])
        : "r"(a[0]), "r"(a[1]), "r"(a[2]), "r"(a[3]), "r"(b[0]), "r"(b[1]));
}

// ===========================================================================
// TF32 tensor-core GEMM:  C[m,n] = sum_k A[m,k]*B[n,k]   (unchanged from R3)
// ===========================================================================
#define BM 128
#define BN 128
#define BK 32
#define PAD 36
#define STAGE_F (128 * PAD)

__global__ __launch_bounds__(256) void tgemm_abT(const float* __restrict__ A,
                                                 const float* __restrict__ B,
                                                 float* __restrict__ C,
                                                 int M, int N, int K)
{
    extern __shared__ float sm[];
    float* As = sm;
    float* Bs = sm + 2 * STAGE_F;

    const int tid  = threadIdx.x;
    const int m0   = blockIdx.y * BM;
    const int n0   = blockIdx.x * BN;
    const int warp = tid >> 5, lane = tid & 31;
    const int wm   = (warp >> 1) * 32;
    const int wn   = (warp & 1) * 64;
    const int g    = lane >> 2;
    const int tg   = lane & 3;

    const int lr = tid >> 3;
    const int lk = (tid & 7) * 4;

    uint32_t sA = (uint32_t)__cvta_generic_to_shared(As);
    uint32_t sB = (uint32_t)__cvta_generic_to_shared(Bs);

    float acc[2][8][4];
#pragma unroll
    for (int mt = 0; mt < 2; mt++)
#pragma unroll
        for (int nt = 0; nt < 8; nt++)
#pragma unroll
            for (int i = 0; i < 4; i++) acc[mt][nt][i] = 0.f;

    const int nk = K / BK;

    auto issue = [&](int stage, int k0) {
        uint32_t da = sA + (stage * STAGE_F) * 4;
        uint32_t db = sB + (stage * STAGE_F) * 4;
#pragma unroll
        for (int h = 0; h < 4; h++) {
            int r = lr + 32 * h;
            cp_async16(da + (r * PAD + lk) * 4,
                       &A[(size_t)(m0 + r) * K + k0 + lk]);
            cp_async16(db + (r * PAD + lk) * 4,
                       &B[(size_t)(n0 + r) * K + k0 + lk]);
        }
        cp_commit();
    };

    issue(0, 0);

    for (int kt = 0; kt < nk; kt++) {
        if (kt + 1 < nk) issue((kt + 1) & 1, (kt + 1) * BK);
        if (kt + 1 < nk) cp_wait<1>(); else cp_wait<0>();
        __syncthreads();

        const float* a_ = As + (kt & 1) * STAGE_F;
        const float* b_ = Bs + (kt & 1) * STAGE_F;

#pragma unroll
        for (int kk = 0; kk < 4; kk++) {
            const int kb = kk * 8 + tg;
            uint32_t af[2][4], bf[8][2];
#pragma unroll
            for (int mt = 0; mt < 2; mt++) {
                int row = wm + mt * 16 + g;
                af[mt][0] = f2tf32(a_[row * PAD + kb]);
                af[mt][1] = f2tf32(a_[(row + 8) * PAD + kb]);
                af[mt][2] = f2tf32(a_[row * PAD + kb + 4]);
                af[mt][3] = f2tf32(a_[(row + 8) * PAD + kb + 4]);
            }
#pragma unroll
            for (int nt = 0; nt < 8; nt++) {
                int col = wn + nt * 8 + g;
                bf[nt][0] = f2tf32(b_[col * PAD + kb]);
                bf[nt][1] = f2tf32(b_[col * PAD + kb + 4]);
            }
#pragma unroll
            for (int mt = 0; mt < 2; mt++)
#pragma unroll
                for (int nt = 0; nt < 8; nt++)
                    mma_tf32(acc[mt][nt], af[mt], bf[nt]);
        }
        __syncthreads();
    }

#pragma unroll
    for (int mt = 0; mt < 2; mt++) {
        int row = m0 + wm + mt * 16 + g;
#pragma unroll
        for (int nt = 0; nt < 8; nt++) {
            int col = n0 + wn + nt * 8 + tg * 2;
            *(float2*)&C[(size_t)row * N + col] =
                make_float2(acc[mt][nt][0], acc[mt][nt][1]);
            *(float2*)&C[(size_t)(row + 8) * N + col] =
                make_float2(acc[mt][nt][2], acc[mt][nt][3]);
        }
    }
}

// ---------------------------------------------------------------------------
// In-place RoPE (value depends only on (s,d); index the [0,0] slice).
// ---------------------------------------------------------------------------
__global__ __launch_bounds__(256) void rope_kernel(float* __restrict__ X,
                                                   int nheads, int rowstride,
                                                   const float* __restrict__ ct,
                                                   const float* __restrict__ st,
                                                   int total)
{
    int idx = blockIdx.x * blockDim.x + threadIdx.x;
    if (idx >= total) return;
    int d = idx & 63;
    int h = (idx >> 6) % nheads;
    int n = idx / (64 * nheads);
    int s = n & (S_ - 1);
    float c1 = ct[s * HD_ + d],      s1 = st[s * HD_ + d];
    float c2 = ct[s * HD_ + d + 64], s2 = st[s * HD_ + d + 64];
    float* p = X + (size_t)n * rowstride + h * HD_;
    float x1 = p[d], x2 = p[d + 64];
    p[d]      = x1 * c1 - x2 * s1;
    p[d + 64] = x2 * c2 + x1 * s2;
}

// ===========================================================================
// Tensor-core flash attention with split-tf32 (hi*hi + hi*lo + lo*hi) for
// both QK^T and PV -> near-fp32 accuracy.  CTA = 128 q-rows of one (b,hq);
// 8 warps x m16; j-tiles of 64.  K/V consumed in natural [j][d] layout.
// smem strides chosen so every fragment LDS is bank-conflict-free.
// ===========================================================================
#define FT_QSTR 132
#define FT_KSTR 132
#define FT_VSTR 136
#define FT_PSTR 68
#define FT_OQ   0
#define FT_OK   (128 * FT_QSTR)            // 16896
#define FT_OV   (FT_OK + 64 * FT_KSTR)     // 25344
#define FT_OP   (FT_OV + 64 * FT_VSTR)     // 34048
#define FT_TOTF (FT_OP + 128 * FT_PSTR)    // 42752 floats = 171008 B

__device__ __forceinline__ void split2(float v, uint32_t& hi, uint32_t& lo) {
    hi = f2tf32(v);
    lo = f2tf32(v - __uint_as_float(hi));
}

__global__ __launch_bounds__(256) void flash_tc(const float* __restrict__ Q,
                                                const float* __restrict__ KV,
                                                float* __restrict__ O)
{
    extern __shared__ float sm[];
    float* sQ = sm + FT_OQ;
    float* sK = sm + FT_OK;
    float* sV = sm + FT_OV;
    float* sP = sm + FT_OP;

    const int tid  = threadIdx.x;
    const int qt   = blockIdx.x;      // 0..15
    const int hq   = blockIdx.y;      // 0..31
    const int b    = blockIdx.z;      // 0..1
    const int hk   = hq >> 2;
    const int i0   = qt * 128;
    const int warp = tid >> 5, lane = tid & 31;
    const int g    = lane >> 2, tg = lane & 3;
    const int wm   = warp * 16;

    uint32_t sbase = (uint32_t)__cvta_generic_to_shared(sm);

    // async-load Q tile [128 x 128]
    const float* qg = Q + ((size_t)(b * S_) + i0) * HID_ + hq * HD_;
#pragma unroll
    for (int it = 0; it < 16; it++) {
        int f = tid + it * 256;
        int r = f >> 5, c = (f & 31) * 4;
        cp_async16(sbase + (uint32_t)(FT_OQ + r * FT_QSTR + c) * 4,
                   qg + (size_t)r * HID_ + c);
    }
    cp_commit();

    float m0 = -1e30f, m1 = -1e30f, l0 = 0.f, l1 = 0.f;
    float accO[16][4];
#pragma unroll
    for (int nt = 0; nt < 16; nt++)
#pragma unroll
        for (int i = 0; i < 4; i++) accO[nt][i] = 0.f;

    const float* kg = KV + (size_t)(b * S_) * 2048 + hk * HD_;
    const float* vg = kg + 1024;
    const float SCALE = 0.08838834764831845f;

    const int ntiles = 2 * qt + 2;
    for (int t = 0; t < ntiles; t++) {
        const int j0 = t * 64;
        __syncthreads();                    // smem safe to overwrite

        // async-load K and V 64-row tiles (natural [j][d] layout)
#pragma unroll
        for (int it = 0; it < 8; it++) {
            int f = tid + it * 256;
            int r = f >> 5, c = (f & 31) * 4;
            cp_async16(sbase + (uint32_t)(FT_OK + r * FT_KSTR + c) * 4,
                       kg + (size_t)(j0 + r) * 2048 + c);
            cp_async16(sbase + (uint32_t)(FT_OV + r * FT_VSTR + c) * 4,
                       vg + (size_t)(j0 + r) * 2048 + c);
        }
        cp_commit();
        cp_wait<0>();
        __syncthreads();                    // tiles (and Q on t=0) ready

        const bool skip = (j0 >= i0 + wm + 16);   // warp fully above diagonal
        if (!skip) {
            // ---- S = Q K^T (split tf32, 3 mma passes) ----
            float sfr[8][4];
#pragma unroll
            for (int nt = 0; nt < 8; nt++)
#pragma unroll
                for (int i = 0; i < 4; i++) sfr[nt][i] = 0.f;

#pragma unroll
            for (int kk = 0; kk < 16; kk++) {
                const int kb = kk * 8 + tg;
                uint32_t ah[4], al[4];
                split2(sQ[(wm + g) * FT_QSTR + kb],     ah[0], al[0]);
                split2(sQ[(wm + g + 8) * FT_QSTR + kb], ah[1], al[1]);
                split2(sQ[(wm + g) * FT_QSTR + kb + 4],     ah[2], al[2]);
                split2(sQ[(wm + g + 8) * FT_QSTR + kb + 4], ah[3], al[3]);
#pragma unroll
                for (int nt = 0; nt < 8; nt++) {
                    uint32_t bh[2], bl[2];
                    split2(sK[(nt * 8 + g) * FT_KSTR + kb],     bh[0], bl[0]);
                    split2(sK[(nt * 8 + g) * FT_KSTR + kb + 4], bh[1], bl[1]);
                    mma_tf32(sfr[nt], ah, bh);
                    mma_tf32(sfr[nt], ah, bl);
                    mma_tf32(sfr[nt], al, bh);
                }
            }

            // ---- scale + causal mask ----
            const int r0g = i0 + wm + g;      // global row of c0/c1
            const int r1g = r0g + 8;          // global row of c2/c3
            const bool dodiag = (t >= 2 * qt);
#pragma unroll
            for (int nt = 0; nt < 8; nt++) {
                int c0 = j0 + nt * 8 + 2 * tg;
#pragma unroll
                for (int i = 0; i < 4; i++) sfr[nt][i] *= SCALE;
                if (dodiag) {
                    if (c0 > r0g)     sfr[nt][0] = -1e30f;
                    if (c0 + 1 > r0g) sfr[nt][1] = -1e30f;
                    if (c0 > r1g)     sfr[nt][2] = -1e30f;
                    if (c0 + 1 > r1g) sfr[nt][3] = -1e30f;
                }
            }

            // ---- online softmax (warp-local, quad reductions) ----
            float mx0 = -1e30f, mx1 = -1e30f;
#pragma unroll
            for (int nt = 0; nt < 8; nt++) {
                mx0 = fmaxf(mx0, fmaxf(sfr[nt][0], sfr[nt][1]));
                mx1 = fmaxf(mx1, fmaxf(sfr[nt][2], sfr[nt][3]));
            }
#pragma unroll
            for (int o = 1; o <= 2; o <<= 1) {
                mx0 = fmaxf(mx0, __shfl_xor_sync(0xffffffffu, mx0, o));
                mx1 = fmaxf(mx1, __shfl_xor_sync(0xffffffffu, mx1, o));
            }
            float mn0 = fmaxf(m0, mx0), mn1 = fmaxf(m1, mx1);
            float cr0 = __expf(m0 - mn0), cr1 = __expf(m1 - mn1);
            float rs0 = 0.f, rs1 = 0.f;
#pragma unroll
            for (int nt = 0; nt < 8; nt++) {
                sfr[nt][0] = __expf(sfr[nt][0] - mn0);
                sfr[nt][1] = __expf(sfr[nt][1] - mn0);
                sfr[nt][2] = __expf(sfr[nt][2] - mn1);
                sfr[nt][3] = __expf(sfr[nt][3] - mn1);
                rs0 += sfr[nt][0] + sfr[nt][1];
                rs1 += sfr[nt][2] + sfr[nt][3];
            }
#pragma unroll
            for (int o = 1; o <= 2; o <<= 1) {
                rs0 += __shfl_xor_sync(0xffffffffu, rs0, o);
                rs1 += __shfl_xor_sync(0xffffffffu, rs1, o);
            }
            l0 = l0 * cr0 + rs0;  m0 = mn0;
            l1 = l1 * cr1 + rs1;  m1 = mn1;
#pragma unroll
            for (int nt = 0; nt < 16; nt++) {
                accO[nt][0] *= cr0; accO[nt][1] *= cr0;
                accO[nt][2] *= cr1; accO[nt][3] *= cr1;
            }
            // ---- P -> smem (own rows only) ----
#pragma unroll
            for (int nt = 0; nt < 8; nt++) {
                *(float2*)&sP[(wm + g) * FT_PSTR + nt * 8 + 2 * tg] =
                    make_float2(sfr[nt][0], sfr[nt][1]);
                *(float2*)&sP[(wm + g + 8) * FT_PSTR + nt * 8 + 2 * tg] =
                    make_float2(sfr[nt][2], sfr[nt][3]);
            }
        }
        __syncwarp();
        if (!skip) {
            // ---- O += P V (split tf32) ----
#pragma unroll
            for (int kk = 0; kk < 8; kk++) {
                const int kb = kk * 8 + tg;
                uint32_t ah[4], al[4];
                split2(sP[(wm + g) * FT_PSTR + kb],     ah[0], al[0]);
                split2(sP[(wm + g + 8) * FT_PSTR + kb], ah[1], al[1]);
                split2(sP[(wm + g) * FT_PSTR + kb + 4],     ah[2], al[2]);
                split2(sP[(wm + g + 8) * FT_PSTR + kb + 4], ah[3], al[3]);
#pragma unroll
                for (int nt = 0; nt < 16; nt++) {
                    uint32_t bh[2], bl[2];
                    split2(sV[kb * FT_VSTR + nt * 8 + g],       bh[0], bl[0]);
                    split2(sV[(kb + 4) * FT_VSTR + nt * 8 + g], bh[1], bl[1]);
                    mma_tf32(accO[nt], ah, bh);
                    mma_tf32(accO[nt], ah, bl);
                    mma_tf32(accO[nt], al, bh);
                }
            }
        }
    }

    // ---- epilogue ----
    const float inv0 = 1.f / l0, inv1 = 1.f / l1;
    float* og = O + ((size_t)(b * S_) + i0) * HID_ + hq * HD_;
#pragma unroll
    for (int nt = 0; nt < 16; nt++) {
        int c0 = nt * 8 + 2 * tg;
        *(float2*)&og[(size_t)(wm + g) * HID_ + c0] =
            make_float2(accO[nt][0] * inv0, accO[nt][1] * inv0);
        *(float2*)&og[(size_t)(wm + g + 8) * HID_ + c0] =
            make_float2(accO[nt][2] * inv1, accO[nt][3] * inv1);
    }
}

// ---------------------------------------------------------------------------
extern "C" void kernel_launch(void* const* d_in, const int* in_sizes, int n_in,
                              void* d_out, int out_size)
{
    const float* x    = (const float*)d_in[0];
    const float* cosT = (const float*)d_in[1];
    const float* sinT = (const float*)d_in[2];
    // d_in[3] = attention_mask (pure causal; handled analytically)
    const float* Wq   = (const float*)d_in[4];
    const float* Wkv  = (const float*)d_in[5];
    const float* Wo   = (const float*)d_in[6];
    float* out = (float*)d_out;

    float *Qp, *KVp, *Ap;
    cudaGetSymbolAddress((void**)&Qp,  g_Q);
    cudaGetSymbolAddress((void**)&KVp, g_KV);
    cudaGetSymbolAddress((void**)&Ap,  g_A);

    const int GEMM_SMEM  = 4 * STAGE_F * 4;     // 73728 B
    const int FT_SMEM    = FT_TOTF * 4;         // 171008 B
    cudaFuncSetAttribute(tgemm_abT,
                         cudaFuncAttributeMaxDynamicSharedMemorySize, GEMM_SMEM);
    cudaFuncSetAttribute(flash_tc,
                         cudaFuncAttributeMaxDynamicSharedMemorySize, FT_SMEM);

    dim3 blk(256);
    // Q = x @ Wq^T            [4096,4096]
    tgemm_abT<<<dim3(32, 32), blk, GEMM_SMEM>>>(x, Wq, Qp, NROW, HID_, HID_);
    // [K|V] = x @ Wkv^T       [4096,2048]
    tgemm_abT<<<dim3(16, 32), blk, GEMM_SMEM>>>(x, Wkv, KVp, NROW, 2048, HID_);
    // RoPE in place
    rope_kernel<<<(NROW * NQ_ * 64) / 256, blk>>>(Qp, NQ_, HID_, cosT, sinT,
                                                  NROW * NQ_ * 64);
    rope_kernel<<<(NROW * NKV_ * 64) / 256, blk>>>(KVp, NKV_, 2048, cosT, sinT,
                                                   NROW * NKV_ * 64);
    // tensor-core causal GQA flash attention -> g_A
    flash_tc<<<dim3(16, NQ_, B_), blk, FT_SMEM>>>(Qp, KVp, Ap);
    // out = A @ Wo^T
    tgemm_abT<<<dim3(32, 32), blk, GEMM_SMEM>>>(Ap, Wo, out, NROW, HID_, HID_);
}